// round 10
// baseline (speedup 1.0000x reference)
#include <cuda_runtime.h>
#include <cuda_fp16.h>
#include <cstdint>
#include <cstddef>

// ---------------------------------------------------------------------------
// BinaryLinear: out[M,N] = x[M,K] @ sign(W)[N,K]^T + bias[N]
// M=8192, N=4096, K=4096 (fp32 in/out).
// Round 10: R8 (best: 128x128 CTA, 8 warps, 64x32 warp tile, frag dbuf)
// with BK=128 / 3 stages to halve barrier frequency and widen the dbuf
// overlap window. 256B smem rows, SW128 swizzle per 128B half.
// ---------------------------------------------------------------------------

#define BM 128
#define BN 128
#define BK 128
#define STAGES 3
#define NTHREADS 256

#define SA_BYTES (BM * BK * 2)   // 32 KB
#define SB_BYTES (BN * BK * 2)   // 32 KB
#define SMEM_TOTAL (STAGES * (SA_BYTES + SB_BYTES))   // 192 KB

// Scratch (device globals: no allocation allowed in kernel_launch)
__device__ __half g_xh[8192u * 4096u];   // x as fp16       [M,K]
__device__ __half g_wh[4096u * 4096u];   // sign(W) as fp16 [N,K]

// ---------------------- conversion kernels ---------------------------------

__global__ void cvt_x_kernel(const float4* __restrict__ x, int n4) {
    __half2* dst = reinterpret_cast<__half2*>(g_xh);
    int stride = gridDim.x * blockDim.x;
    for (int i = blockIdx.x * blockDim.x + threadIdx.x; i < n4; i += stride) {
        float4 v = x[i];
        dst[2 * i + 0] = __floats2half2_rn(v.x, v.y);
        dst[2 * i + 1] = __floats2half2_rn(v.z, v.w);
    }
}

__device__ __forceinline__ float fsign(float v) {
    return (v > 0.0f) ? 1.0f : ((v < 0.0f) ? -1.0f : 0.0f);
}

__global__ void cvt_w_kernel(const float4* __restrict__ w, int n4) {
    __half2* dst = reinterpret_cast<__half2*>(g_wh);
    int stride = gridDim.x * blockDim.x;
    for (int i = blockIdx.x * blockDim.x + threadIdx.x; i < n4; i += stride) {
        float4 v = w[i];
        dst[2 * i + 0] = __floats2half2_rn(fsign(v.x), fsign(v.y));
        dst[2 * i + 1] = __floats2half2_rn(fsign(v.z), fsign(v.w));
    }
}

// ---------------------- GEMM helpers ---------------------------------------

__device__ __forceinline__ void cp_async16(uint32_t saddr, const void* gaddr) {
    asm volatile("cp.async.cg.shared.global [%0], [%1], 16;\n"
                 :: "r"(saddr), "l"(gaddr));
}
__device__ __forceinline__ void cp_commit() {
    asm volatile("cp.async.commit_group;\n");
}
template <int N>
__device__ __forceinline__ void cp_wait() {
    asm volatile("cp.async.wait_group %0;\n" :: "n"(N));
}

__device__ __forceinline__ void ldsm4(uint32_t& r0, uint32_t& r1,
                                      uint32_t& r2, uint32_t& r3,
                                      uint32_t addr) {
    asm volatile("ldmatrix.sync.aligned.m8n8.x4.shared.b16 {%0,%1,%2,%3}, [%4];\n"
                 : "=r"(r0), "=r"(r1), "=r"(r2), "=r"(r3)
                 : "r"(addr));
}

__device__ __forceinline__ void mma16816(float* d, const uint32_t* a, const uint32_t* b) {
    asm volatile("mma.sync.aligned.m16n8k16.row.col.f32.f16.f16.f32 "
                 "{%0,%1,%2,%3}, {%4,%5,%6,%7}, {%8,%9}, {%0,%1,%2,%3};\n"
                 : "+f"(d[0]), "+f"(d[1]), "+f"(d[2]), "+f"(d[3])
                 : "r"(a[0]), "r"(a[1]), "r"(a[2]), "r"(a[3]),
                   "r"(b[0]), "r"(b[1]));
}

// swizzled byte offset within a tile for (row, 16B-chunk), 256B rows.
// SW128 applied within each 128B half: chunk' = (chunk&8) | ((chunk&7)^(row&7))
__device__ __forceinline__ uint32_t swz(int row, int chunk) {
    return (uint32_t)(row * 256 + ((chunk & 8) << 4) + ((((chunk & 7) ^ (row & 7))) << 4));
}

// issue cp.async loads for (A,B) slab kt into pipeline stage s.
// 256 threads: thread t -> row t>>1, chunks (t&1)*8 .. +7 (8x16B) of A and B.
__device__ __forceinline__ void load_tiles(int kt, int s, int NK,
                                           int bm, int bn, int K,
                                           uint32_t sA, uint32_t sB, int tid) {
    if (kt < NK) {
        int row = tid >> 1;          // 0..127
        int c0 = (tid & 1) * 8;      // 0 or 8
        const __half* Ag = g_xh + (size_t)(bm + row) * K + (size_t)kt * BK + c0 * 8;
        uint32_t da = sA + s * SA_BYTES;
#pragma unroll
        for (int c = 0; c < 8; c++)
            cp_async16(da + swz(row, c0 + c), Ag + c * 8);
        const __half* Bg = g_wh + (size_t)(bn + row) * K + (size_t)kt * BK + c0 * 8;
        uint32_t db = sB + s * SB_BYTES;
#pragma unroll
        for (int c = 0; c < 8; c++)
            cp_async16(db + swz(row, c0 + c), Bg + c * 8);
    }
    cp_commit();
}

// load A+B fragments for one 16-wide k-step (ks in 0..7) from stage s
__device__ __forceinline__ void load_frags(uint32_t a[4][4], uint32_t b[4][2],
                                           int ks, int s, int wm, int wn,
                                           int lane, uint32_t sA, uint32_t sB) {
#pragma unroll
    for (int mi = 0; mi < 4; mi++) {
        int row = wm * 64 + mi * 16 + (lane & 15);
        int chunk = 2 * ks + (lane >> 4);
        uint32_t addr = sA + s * SA_BYTES + swz(row, chunk);
        ldsm4(a[mi][0], a[mi][1], a[mi][2], a[mi][3], addr);
    }
#pragma unroll
    for (int nj = 0; nj < 2; nj++) {
        int row = wn * 32 + nj * 16 + (lane & 7) + ((lane >> 4) << 3);
        int chunk = 2 * ks + ((lane >> 3) & 1);
        uint32_t addr = sB + s * SB_BYTES + swz(row, chunk);
        ldsm4(b[2 * nj][0], b[2 * nj][1], b[2 * nj + 1][0], b[2 * nj + 1][1], addr);
    }
}

// ---------------------- GEMM kernel -----------------------------------------
// 256 threads = 8 warps laid out 2(M) x 4(N). Warp tile 64x32.
// Fragments double-buffered across ks; BK=128 -> 32 barriers total.

__global__ __launch_bounds__(NTHREADS, 1)
void bgemm_kernel(const float* __restrict__ bias, float* __restrict__ C,
                  int M, int N, int K) {
    extern __shared__ __align__(128) unsigned char smem_raw[];
    uint32_t sbase = (uint32_t)__cvta_generic_to_shared(smem_raw);
    uint32_t sA = sbase;
    uint32_t sB = sbase + STAGES * SA_BYTES;

    int tid = threadIdx.x;
    int lane = tid & 31;
    int wid = tid >> 5;
    int wm = wid >> 2;          // 0..1
    int wn = wid & 3;           // 0..3
    int bm = blockIdx.y * BM;
    int bn = blockIdx.x * BN;

    int NK = K / BK;            // 32

#pragma unroll
    for (int s = 0; s < STAGES - 1; s++)
        load_tiles(s, s, NK, bm, bn, K, sA, sB, tid);

    float acc[4][4][4];
#pragma unroll
    for (int mi = 0; mi < 4; mi++)
#pragma unroll
        for (int ni = 0; ni < 4; ni++)
#pragma unroll
            for (int r = 0; r < 4; r++) acc[mi][ni][r] = 0.0f;

    uint32_t a[2][4][4], b[2][4][2];

    int s = 0;
    for (int kt = 0; kt < NK; kt++) {
        cp_wait<STAGES - 2>();
        __syncthreads();   // stage s resident; oldest stage free

        load_tiles(kt + STAGES - 1, (kt + STAGES - 1) % STAGES, NK,
                   bm, bn, K, sA, sB, tid);

        load_frags(a[0], b[0], 0, s, wm, wn, lane, sA, sB);
#pragma unroll
        for (int ks = 0; ks < BK / 16; ks++) {
            int cur = ks & 1;
            if (ks < BK / 16 - 1)
                load_frags(a[cur ^ 1], b[cur ^ 1], ks + 1, s, wm, wn, lane, sA, sB);
#pragma unroll
            for (int mi = 0; mi < 4; mi++)
#pragma unroll
                for (int ni = 0; ni < 4; ni++)
                    mma16816(acc[mi][ni], a[cur][mi], b[cur][ni]);
        }
        s = (s + 1 == STAGES) ? 0 : s + 1;
    }

    cp_wait<0>();

    // epilogue: add bias, store fp32
    int crow = bm + wm * 64;
    int ccol = bn + wn * 32;
#pragma unroll
    for (int mi = 0; mi < 4; mi++) {
        int r = crow + mi * 16 + (lane >> 2);
#pragma unroll
        for (int ni = 0; ni < 4; ni++) {
            int c = ccol + ni * 8 + (lane & 3) * 2;
            float b0 = bias[c], b1 = bias[c + 1];
            float2 v0 = make_float2(acc[mi][ni][0] + b0, acc[mi][ni][1] + b1);
            float2 v1 = make_float2(acc[mi][ni][2] + b0, acc[mi][ni][3] + b1);
            *reinterpret_cast<float2*>(C + (size_t)r * N + c) = v0;
            *reinterpret_cast<float2*>(C + (size_t)(r + 8) * N + c) = v1;
        }
    }
}

// ---------------------- launch ----------------------------------------------

extern "C" void kernel_launch(void* const* d_in, const int* in_sizes, int n_in,
                              void* d_out, int out_size) {
    const float* x = (const float*)d_in[0];     // [M,K] fp32
    const float* w = (const float*)d_in[1];     // [N,K] fp32
    const float* bias = (const float*)d_in[2];  // [N]   fp32
    float* out = (float*)d_out;                 // [M,N] fp32

    int N = in_sizes[2];
    int K = in_sizes[1] / N;
    int M = in_sizes[0] / K;

    cvt_x_kernel<<<4096, 256>>>((const float4*)x, (M * K) / 4);
    cvt_w_kernel<<<4096, 256>>>((const float4*)w, (N * K) / 4);

    // Persistent attribute; harmless outside capture, inherited by capture.
    cudaFuncSetAttribute(bgemm_kernel,
                         cudaFuncAttributeMaxDynamicSharedMemorySize, SMEM_TOTAL);

    dim3 grid(N / BN, M / BM);
    bgemm_kernel<<<grid, NTHREADS, SMEM_TOTAL>>>(bias, out, M, N, K);
}

// round 11
// speedup vs baseline: 1.9166x; 1.9166x over previous
#include <cuda_runtime.h>
#include <cuda_fp16.h>
#include <cstdint>
#include <cstddef>

// ---------------------------------------------------------------------------
// BinaryLinear: out[M,N] = x[M,K] @ sign(W)[N,K]^T + bias[N]
// M=8192, N=4096, K=4096 (fp32 in/out).
// Round 11: R8 (best, 768us) + scheduling micro-opts only:
//   - per-kt body reordered: first frag ldsm issues BEFORE the cp.async
//     burst, so the loader overlaps MMA instead of delaying the critical path
//   - STAGES 4 -> 5 (160 KB smem) for DRAM-jitter absorption
//   - bias loads hoisted in the epilogue
// Geometry unchanged: 128x128 CTA, 8 warps (2Mx4N), warp tile 64x32, BK=64,
// SW128 swizzle, fragment double-buffering, fp16 operands, fp32 accumulate.
// ---------------------------------------------------------------------------

#define BM 128
#define BN 128
#define BK 64
#define STAGES 5
#define NTHREADS 256

#define SA_BYTES (BM * BK * 2)   // 16 KB
#define SB_BYTES (BN * BK * 2)   // 16 KB
#define SMEM_TOTAL (STAGES * (SA_BYTES + SB_BYTES))   // 160 KB

// Scratch (device globals: no allocation allowed in kernel_launch)
__device__ __half g_xh[8192u * 4096u];   // x as fp16       [M,K]
__device__ __half g_wh[4096u * 4096u];   // sign(W) as fp16 [N,K]

// ---------------------- conversion kernels ---------------------------------

__global__ void cvt_x_kernel(const float4* __restrict__ x, int n4) {
    __half2* dst = reinterpret_cast<__half2*>(g_xh);
    int stride = gridDim.x * blockDim.x;
    for (int i = blockIdx.x * blockDim.x + threadIdx.x; i < n4; i += stride) {
        float4 v = x[i];
        dst[2 * i + 0] = __floats2half2_rn(v.x, v.y);
        dst[2 * i + 1] = __floats2half2_rn(v.z, v.w);
    }
}

__device__ __forceinline__ float fsign(float v) {
    return (v > 0.0f) ? 1.0f : ((v < 0.0f) ? -1.0f : 0.0f);
}

__global__ void cvt_w_kernel(const float4* __restrict__ w, int n4) {
    __half2* dst = reinterpret_cast<__half2*>(g_wh);
    int stride = gridDim.x * blockDim.x;
    for (int i = blockIdx.x * blockDim.x + threadIdx.x; i < n4; i += stride) {
        float4 v = w[i];
        dst[2 * i + 0] = __floats2half2_rn(fsign(v.x), fsign(v.y));
        dst[2 * i + 1] = __floats2half2_rn(fsign(v.z), fsign(v.w));
    }
}

// ---------------------- GEMM helpers ---------------------------------------

__device__ __forceinline__ void cp_async16(uint32_t saddr, const void* gaddr) {
    asm volatile("cp.async.cg.shared.global [%0], [%1], 16;\n"
                 :: "r"(saddr), "l"(gaddr));
}
__device__ __forceinline__ void cp_commit() {
    asm volatile("cp.async.commit_group;\n");
}
template <int N>
__device__ __forceinline__ void cp_wait() {
    asm volatile("cp.async.wait_group %0;\n" :: "n"(N));
}

__device__ __forceinline__ void ldsm4(uint32_t& r0, uint32_t& r1,
                                      uint32_t& r2, uint32_t& r3,
                                      uint32_t addr) {
    asm volatile("ldmatrix.sync.aligned.m8n8.x4.shared.b16 {%0,%1,%2,%3}, [%4];\n"
                 : "=r"(r0), "=r"(r1), "=r"(r2), "=r"(r3)
                 : "r"(addr));
}

__device__ __forceinline__ void mma16816(float* d, const uint32_t* a, const uint32_t* b) {
    asm volatile("mma.sync.aligned.m16n8k16.row.col.f32.f16.f16.f32 "
                 "{%0,%1,%2,%3}, {%4,%5,%6,%7}, {%8,%9}, {%0,%1,%2,%3};\n"
                 : "+f"(d[0]), "+f"(d[1]), "+f"(d[2]), "+f"(d[3])
                 : "r"(a[0]), "r"(a[1]), "r"(a[2]), "r"(a[3]),
                   "r"(b[0]), "r"(b[1]));
}

// issue cp.async loads for (A,B) tile kt into pipeline stage s (R1/R8 loader).
__device__ __forceinline__ void load_tiles(int kt, int s, int NK,
                                           int bm, int bn, int K,
                                           uint32_t sA, uint32_t sB,
                                           int ld_row, int ld_chunk) {
    if (kt < NK) {
        const __half* Ag = g_xh;
        const __half* Bg = g_wh;
#pragma unroll
        for (int p = 0; p < 4; p++) {
            int row = ld_row + p * 32;
            uint32_t da = sA + s * SA_BYTES + row * 128 + ((ld_chunk ^ (row & 7)) << 4);
            const void* ga = Ag + (size_t)(bm + row) * K + (size_t)kt * BK + ld_chunk * 8;
            cp_async16(da, ga);
        }
#pragma unroll
        for (int p = 0; p < 4; p++) {
            int row = ld_row + p * 32;
            uint32_t db = sB + s * SB_BYTES + row * 128 + ((ld_chunk ^ (row & 7)) << 4);
            const void* gb = Bg + (size_t)(bn + row) * K + (size_t)kt * BK + ld_chunk * 8;
            cp_async16(db, gb);
        }
    }
    cp_commit();
}

// load A+B fragments for one 16-wide k-step from stage s
__device__ __forceinline__ void load_frags(uint32_t a[4][4], uint32_t b[4][2],
                                           int ks, int s, int wm, int wn,
                                           int lane, uint32_t sA, uint32_t sB) {
#pragma unroll
    for (int mi = 0; mi < 4; mi++) {
        int row = wm * 64 + mi * 16 + (lane & 15);
        int chunk = 2 * ks + (lane >> 4);
        uint32_t addr = sA + s * SA_BYTES + row * 128 + ((chunk ^ (row & 7)) << 4);
        ldsm4(a[mi][0], a[mi][1], a[mi][2], a[mi][3], addr);
    }
#pragma unroll
    for (int nj = 0; nj < 2; nj++) {
        int row = wn * 32 + nj * 16 + (lane & 7) + ((lane >> 4) << 3);
        int chunk = 2 * ks + ((lane >> 3) & 1);
        uint32_t addr = sB + s * SB_BYTES + row * 128 + ((chunk ^ (row & 7)) << 4);
        ldsm4(b[2 * nj][0], b[2 * nj][1], b[2 * nj + 1][0], b[2 * nj + 1][1], addr);
    }
}

// ---------------------- GEMM kernel -----------------------------------------
// 256 threads = 8 warps laid out 2(M) x 4(N). Warp tile 64x32.
// Fragments double-buffered across ks so LDSM overlaps MMA.

__global__ __launch_bounds__(NTHREADS, 1)
void bgemm_kernel(const float* __restrict__ bias, float* __restrict__ C,
                  int M, int N, int K) {
    extern __shared__ __align__(128) unsigned char smem_raw[];
    uint32_t sbase = (uint32_t)__cvta_generic_to_shared(smem_raw);
    uint32_t sA = sbase;
    uint32_t sB = sbase + STAGES * SA_BYTES;

    int tid = threadIdx.x;
    int lane = tid & 31;
    int wid = tid >> 5;
    int wm = wid >> 2;          // 0..1
    int wn = wid & 3;           // 0..3
    int bm = blockIdx.y * BM;
    int bn = blockIdx.x * BN;

    int ld_row = tid >> 3;      // 0..31
    int ld_chunk = tid & 7;     // 0..7

    int NK = K / BK;

#pragma unroll
    for (int s = 0; s < STAGES - 1; s++)
        load_tiles(s, s, NK, bm, bn, K, sA, sB, ld_row, ld_chunk);

    float acc[4][4][4];
#pragma unroll
    for (int mi = 0; mi < 4; mi++)
#pragma unroll
        for (int ni = 0; ni < 4; ni++)
#pragma unroll
            for (int r = 0; r < 4; r++) acc[mi][ni][r] = 0.0f;

    uint32_t a[2][4][4], b[2][4][2];

    int s = 0;
    for (int kt = 0; kt < NK; kt++) {
        cp_wait<STAGES - 2>();
        __syncthreads();

        // critical path first: fragments for ks=0 of this stage
        load_frags(a[0], b[0], 0, s, wm, wn, lane, sA, sB);

        // cp.async burst for the incoming stage overlaps the mma loop below
        load_tiles(kt + STAGES - 1, (kt + STAGES - 1) % STAGES, NK,
                   bm, bn, K, sA, sB, ld_row, ld_chunk);

#pragma unroll
        for (int ks = 0; ks < BK / 16; ks++) {
            int cur = ks & 1;
            if (ks < BK / 16 - 1)
                load_frags(a[cur ^ 1], b[cur ^ 1], ks + 1, s, wm, wn, lane, sA, sB);
#pragma unroll
            for (int mi = 0; mi < 4; mi++)
#pragma unroll
                for (int ni = 0; ni < 4; ni++)
                    mma16816(acc[mi][ni], a[cur][mi], b[cur][ni]);
        }
        s = (s + 1 == STAGES) ? 0 : s + 1;
    }

    cp_wait<0>();

    // epilogue: add bias (hoisted — mi-invariant), store fp32
    int crow = bm + wm * 64;
    int ccol = bn + wn * 32;
    float bh[4][2];
#pragma unroll
    for (int ni = 0; ni < 4; ni++) {
        int c = ccol + ni * 8 + (lane & 3) * 2;
        bh[ni][0] = bias[c];
        bh[ni][1] = bias[c + 1];
    }
#pragma unroll
    for (int mi = 0; mi < 4; mi++) {
        int r = crow + mi * 16 + (lane >> 2);
#pragma unroll
        for (int ni = 0; ni < 4; ni++) {
            int c = ccol + ni * 8 + (lane & 3) * 2;
            float2 v0 = make_float2(acc[mi][ni][0] + bh[ni][0], acc[mi][ni][1] + bh[ni][1]);
            float2 v1 = make_float2(acc[mi][ni][2] + bh[ni][0], acc[mi][ni][3] + bh[ni][1]);
            *reinterpret_cast<float2*>(C + (size_t)r * N + c) = v0;
            *reinterpret_cast<float2*>(C + (size_t)(r + 8) * N + c) = v1;
        }
    }
}

// ---------------------- launch ----------------------------------------------

extern "C" void kernel_launch(void* const* d_in, const int* in_sizes, int n_in,
                              void* d_out, int out_size) {
    const float* x = (const float*)d_in[0];     // [M,K] fp32
    const float* w = (const float*)d_in[1];     // [N,K] fp32
    const float* bias = (const float*)d_in[2];  // [N]   fp32
    float* out = (float*)d_out;                 // [M,N] fp32

    int N = in_sizes[2];
    int K = in_sizes[1] / N;
    int M = in_sizes[0] / K;

    cvt_x_kernel<<<4096, 256>>>((const float4*)x, (M * K) / 4);
    cvt_w_kernel<<<4096, 256>>>((const float4*)w, (N * K) / 4);

    // Persistent attribute; harmless outside capture, inherited by capture.
    cudaFuncSetAttribute(bgemm_kernel,
                         cudaFuncAttributeMaxDynamicSharedMemorySize, SMEM_TOTAL);

    dim3 grid(N / BN, M / BM);
    bgemm_kernel<<<grid, NTHREADS, SMEM_TOTAL>>>(bias, out, M, N, K);
}

// round 12
// speedup vs baseline: 2.0790x; 1.0847x over previous
#include <cuda_runtime.h>
#include <cuda_fp16.h>
#include <cstdint>
#include <cstddef>

// ---------------------------------------------------------------------------
// BinaryLinear: out[M,N] = x[M,K] @ sign(W)[N,K]^T + bias[N]
// M=8192, N=4096, K=4096 (fp32 in/out).
// Round 12: R8 geometry exactly (128x128 CTA, 8 warps 2Mx4N, 64x32 warp tile,
// BK=64, SW128, frag dbuf) with the kt-loop unrolled by 2 over a 6-stage
// ring: ONE cp_wait+__syncthreads per TWO k-slabs (32 barriers total).
// Loader and mma code unchanged from R8 — isolates the barrier-frequency
// variable that R10 confounded.
// ---------------------------------------------------------------------------

#define BM 128
#define BN 128
#define BK 64
#define STAGES 6
#define NTHREADS 256

#define SA_BYTES (BM * BK * 2)   // 16 KB
#define SB_BYTES (BN * BK * 2)   // 16 KB
#define SMEM_TOTAL (STAGES * (SA_BYTES + SB_BYTES))   // 192 KB

// Scratch (device globals: no allocation allowed in kernel_launch)
__device__ __half g_xh[8192u * 4096u];   // x as fp16       [M,K]
__device__ __half g_wh[4096u * 4096u];   // sign(W) as fp16 [N,K]

// ---------------------- conversion kernels ---------------------------------

__global__ void cvt_x_kernel(const float4* __restrict__ x, int n4) {
    __half2* dst = reinterpret_cast<__half2*>(g_xh);
    int stride = gridDim.x * blockDim.x;
    for (int i = blockIdx.x * blockDim.x + threadIdx.x; i < n4; i += stride) {
        float4 v = x[i];
        dst[2 * i + 0] = __floats2half2_rn(v.x, v.y);
        dst[2 * i + 1] = __floats2half2_rn(v.z, v.w);
    }
}

__device__ __forceinline__ float fsign(float v) {
    return (v > 0.0f) ? 1.0f : ((v < 0.0f) ? -1.0f : 0.0f);
}

__global__ void cvt_w_kernel(const float4* __restrict__ w, int n4) {
    __half2* dst = reinterpret_cast<__half2*>(g_wh);
    int stride = gridDim.x * blockDim.x;
    for (int i = blockIdx.x * blockDim.x + threadIdx.x; i < n4; i += stride) {
        float4 v = w[i];
        dst[2 * i + 0] = __floats2half2_rn(fsign(v.x), fsign(v.y));
        dst[2 * i + 1] = __floats2half2_rn(fsign(v.z), fsign(v.w));
    }
}

// ---------------------- GEMM helpers ---------------------------------------

__device__ __forceinline__ void cp_async16(uint32_t saddr, const void* gaddr) {
    asm volatile("cp.async.cg.shared.global [%0], [%1], 16;\n"
                 :: "r"(saddr), "l"(gaddr));
}
__device__ __forceinline__ void cp_commit() {
    asm volatile("cp.async.commit_group;\n");
}
template <int N>
__device__ __forceinline__ void cp_wait() {
    asm volatile("cp.async.wait_group %0;\n" :: "n"(N));
}

__device__ __forceinline__ void ldsm4(uint32_t& r0, uint32_t& r1,
                                      uint32_t& r2, uint32_t& r3,
                                      uint32_t addr) {
    asm volatile("ldmatrix.sync.aligned.m8n8.x4.shared.b16 {%0,%1,%2,%3}, [%4];\n"
                 : "=r"(r0), "=r"(r1), "=r"(r2), "=r"(r3)
                 : "r"(addr));
}

__device__ __forceinline__ void mma16816(float* d, const uint32_t* a, const uint32_t* b) {
    asm volatile("mma.sync.aligned.m16n8k16.row.col.f32.f16.f16.f32 "
                 "{%0,%1,%2,%3}, {%4,%5,%6,%7}, {%8,%9}, {%0,%1,%2,%3};\n"
                 : "+f"(d[0]), "+f"(d[1]), "+f"(d[2]), "+f"(d[3])
                 : "r"(a[0]), "r"(a[1]), "r"(a[2]), "r"(a[3]),
                   "r"(b[0]), "r"(b[1]));
}

// issue cp.async loads for (A,B) tile kt into pipeline stage s (R8 loader).
__device__ __forceinline__ void load_tiles(int kt, int s, int NK,
                                           int bm, int bn, int K,
                                           uint32_t sA, uint32_t sB,
                                           int ld_row, int ld_chunk) {
    if (kt < NK) {
        const __half* Ag = g_xh;
        const __half* Bg = g_wh;
#pragma unroll
        for (int p = 0; p < 4; p++) {
            int row = ld_row + p * 32;
            uint32_t da = sA + s * SA_BYTES + row * 128 + ((ld_chunk ^ (row & 7)) << 4);
            const void* ga = Ag + (size_t)(bm + row) * K + (size_t)kt * BK + ld_chunk * 8;
            cp_async16(da, ga);
        }
#pragma unroll
        for (int p = 0; p < 4; p++) {
            int row = ld_row + p * 32;
            uint32_t db = sB + s * SB_BYTES + row * 128 + ((ld_chunk ^ (row & 7)) << 4);
            const void* gb = Bg + (size_t)(bn + row) * K + (size_t)kt * BK + ld_chunk * 8;
            cp_async16(db, gb);
        }
    }
    cp_commit();
}

// load A+B fragments for one 16-wide k-step from stage s (R8 code)
__device__ __forceinline__ void load_frags(uint32_t a[4][4], uint32_t b[4][2],
                                           int ks, int s, int wm, int wn,
                                           int lane, uint32_t sA, uint32_t sB) {
#pragma unroll
    for (int mi = 0; mi < 4; mi++) {
        int row = wm * 64 + mi * 16 + (lane & 15);
        int chunk = 2 * ks + (lane >> 4);
        uint32_t addr = sA + s * SA_BYTES + row * 128 + ((chunk ^ (row & 7)) << 4);
        ldsm4(a[mi][0], a[mi][1], a[mi][2], a[mi][3], addr);
    }
#pragma unroll
    for (int nj = 0; nj < 2; nj++) {
        int row = wn * 32 + nj * 16 + (lane & 7) + ((lane >> 4) << 3);
        int chunk = 2 * ks + ((lane >> 3) & 1);
        uint32_t addr = sB + s * SB_BYTES + row * 128 + ((chunk ^ (row & 7)) << 4);
        ldsm4(b[2 * nj][0], b[2 * nj][1], b[2 * nj + 1][0], b[2 * nj + 1][1], addr);
    }
}

// ---------------------- GEMM kernel -----------------------------------------
// 256 threads = 8 warps laid out 2(M) x 4(N). Warp tile 64x32.
// kt-loop unrolled x2 over a 6-stage ring; frag dbuf chains across the
// two stages (8 ks steps per barrier).

__global__ __launch_bounds__(NTHREADS, 1)
void bgemm_kernel(const float* __restrict__ bias, float* __restrict__ C,
                  int M, int N, int K) {
    extern __shared__ __align__(128) unsigned char smem_raw[];
    uint32_t sbase = (uint32_t)__cvta_generic_to_shared(smem_raw);
    uint32_t sA = sbase;
    uint32_t sB = sbase + STAGES * SA_BYTES;

    int tid = threadIdx.x;
    int lane = tid & 31;
    int wid = tid >> 5;
    int wm = wid >> 2;          // 0..1
    int wn = wid & 3;           // 0..3
    int bm = blockIdx.y * BM;
    int bn = blockIdx.x * BN;

    int ld_row = tid >> 3;      // 0..31
    int ld_chunk = tid & 7;     // 0..7

    int NK = K / BK;            // 64 (even; NK/2 = 32 outer iters)

    // prologue: fill stages 0..3 (4 commit groups)
#pragma unroll
    for (int s = 0; s < 4; s++)
        load_tiles(s, s, NK, bm, bn, K, sA, sB, ld_row, ld_chunk);

    float acc[4][4][4];
#pragma unroll
    for (int mi = 0; mi < 4; mi++)
#pragma unroll
        for (int ni = 0; ni < 4; ni++)
#pragma unroll
            for (int r = 0; r < 4; r++) acc[mi][ni][r] = 0.0f;

    uint32_t a[2][4][4], b[2][4][2];

    for (int j = 0; j < NK / 2; j++) {
        int kt0 = 2 * j;
        int s0 = kt0 % STAGES;
        int s1 = (kt0 + 1) % STAGES;

        // wait until stages s0 and s1 are resident (<=2 groups outstanding)
        cp_wait<2>();
        __syncthreads();

        // critical path first: frags for (s0, ks=0)
        load_frags(a[0], b[0], 0, s0, wm, wn, lane, sA, sB);

        // issue loads for slabs kt0+4, kt0+5 (stages (kt0+4)%6, (kt0+5)%6 —
        // distinct from s0,s1 and the two pending stages)
        load_tiles(kt0 + 4, (kt0 + 4) % STAGES, NK, bm, bn, K, sA, sB, ld_row, ld_chunk);
        load_tiles(kt0 + 5, (kt0 + 5) % STAGES, NK, bm, bn, K, sA, sB, ld_row, ld_chunk);

        // 8 ks steps spanning stages s0 (steps 0-3) and s1 (steps 4-7),
        // with fragment double-buffering chained across the boundary.
#pragma unroll
        for (int step = 0; step < 8; step++) {
            int cur = step & 1;
            if (step < 7) {
                int nstep = step + 1;
                int ns = (nstep < 4) ? s0 : s1;
                load_frags(a[cur ^ 1], b[cur ^ 1], nstep & 3, ns, wm, wn, lane, sA, sB);
            }
#pragma unroll
            for (int mi = 0; mi < 4; mi++)
#pragma unroll
                for (int ni = 0; ni < 4; ni++)
                    mma16816(acc[mi][ni], a[cur][mi], b[cur][ni]);
        }
    }

    cp_wait<0>();

    // epilogue: add bias (hoisted), store fp32
    int crow = bm + wm * 64;
    int ccol = bn + wn * 32;
    float bh[4][2];
#pragma unroll
    for (int ni = 0; ni < 4; ni++) {
        int c = ccol + ni * 8 + (lane & 3) * 2;
        bh[ni][0] = bias[c];
        bh[ni][1] = bias[c + 1];
    }
#pragma unroll
    for (int mi = 0; mi < 4; mi++) {
        int r = crow + mi * 16 + (lane >> 2);
#pragma unroll
        for (int ni = 0; ni < 4; ni++) {
            int c = ccol + ni * 8 + (lane & 3) * 2;
            float2 v0 = make_float2(acc[mi][ni][0] + bh[ni][0], acc[mi][ni][1] + bh[ni][1]);
            float2 v1 = make_float2(acc[mi][ni][2] + bh[ni][0], acc[mi][ni][3] + bh[ni][1]);
            *reinterpret_cast<float2*>(C + (size_t)r * N + c) = v0;
            *reinterpret_cast<float2*>(C + (size_t)(r + 8) * N + c) = v1;
        }
    }
}

// ---------------------- launch ----------------------------------------------

extern "C" void kernel_launch(void* const* d_in, const int* in_sizes, int n_in,
                              void* d_out, int out_size) {
    const float* x = (const float*)d_in[0];     // [M,K] fp32
    const float* w = (const float*)d_in[1];     // [N,K] fp32
    const float* bias = (const float*)d_in[2];  // [N]   fp32
    float* out = (float*)d_out;                 // [M,N] fp32

    int N = in_sizes[2];
    int K = in_sizes[1] / N;
    int M = in_sizes[0] / K;

    cvt_x_kernel<<<4096, 256>>>((const float4*)x, (M * K) / 4);
    cvt_w_kernel<<<4096, 256>>>((const float4*)w, (N * K) / 4);

    // Persistent attribute; harmless outside capture, inherited by capture.
    cudaFuncSetAttribute(bgemm_kernel,
                         cudaFuncAttributeMaxDynamicSharedMemorySize, SMEM_TOTAL);

    dim3 grid(N / BN, M / BM);
    bgemm_kernel<<<grid, NTHREADS, SMEM_TOTAL>>>(bias, out, M, N, K);
}

// round 15
// speedup vs baseline: 2.0973x; 1.0088x over previous
#include <cuda_runtime.h>
#include <cuda_fp16.h>
#include <cstdint>
#include <cstddef>

// ---------------------------------------------------------------------------
// BinaryLinear: out[M,N] = x[M,K] @ sign(W)[N,K]^T + bias[N]
// M=8192, N=4096, K=4096 (fp32 in/out).
// Round 13: R12 (708us: 128x128 CTA, 8 warps 2Mx4N, 64x32 warp tile, BK=64,
// kt-unroll x2) with:
//   - STAGES 6 -> 7 (224 KB): prefetch distance 5, cp_wait<3> (one more
//     slab of latency absorption)
//   - second cp.async burst deferred into the mma stream (spread LDGSTS,
//     avoid front-batched L1tex queue pressure)
// ---------------------------------------------------------------------------

#define BM 128
#define BN 128
#define BK 64
#define STAGES 7
#define NTHREADS 256

#define SA_BYTES (BM * BK * 2)   // 16 KB
#define SB_BYTES (BN * BK * 2)   // 16 KB
#define SMEM_TOTAL (STAGES * (SA_BYTES + SB_BYTES))   // 224 KB

// Scratch (device globals: no allocation allowed in kernel_launch)
__device__ __half g_xh[8192u * 4096u];   // x as fp16       [M,K]
__device__ __half g_wh[4096u * 4096u];   // sign(W) as fp16 [N,K]

// ---------------------- conversion kernels ---------------------------------

__global__ void cvt_x_kernel(const float4* __restrict__ x, int n4) {
    __half2* dst = reinterpret_cast<__half2*>(g_xh);
    int stride = gridDim.x * blockDim.x;
    for (int i = blockIdx.x * blockDim.x + threadIdx.x; i < n4; i += stride) {
        float4 v = x[i];
        dst[2 * i + 0] = __floats2half2_rn(v.x, v.y);
        dst[2 * i + 1] = __floats2half2_rn(v.z, v.w);
    }
}

__device__ __forceinline__ float fsign(float v) {
    return (v > 0.0f) ? 1.0f : ((v < 0.0f) ? -1.0f : 0.0f);
}

__global__ void cvt_w_kernel(const float4* __restrict__ w, int n4) {
    __half2* dst = reinterpret_cast<__half2*>(g_wh);
    int stride = gridDim.x * blockDim.x;
    for (int i = blockIdx.x * blockDim.x + threadIdx.x; i < n4; i += stride) {
        float4 v = w[i];
        dst[2 * i + 0] = __floats2half2_rn(fsign(v.x), fsign(v.y));
        dst[2 * i + 1] = __floats2half2_rn(fsign(v.z), fsign(v.w));
    }
}

// ---------------------- GEMM helpers ---------------------------------------

__device__ __forceinline__ void cp_async16(uint32_t saddr, const void* gaddr) {
    asm volatile("cp.async.cg.shared.global [%0], [%1], 16;\n"
                 :: "r"(saddr), "l"(gaddr));
}
__device__ __forceinline__ void cp_commit() {
    asm volatile("cp.async.commit_group;\n");
}
template <int N>
__device__ __forceinline__ void cp_wait() {
    asm volatile("cp.async.wait_group %0;\n" :: "n"(N));
}

__device__ __forceinline__ void ldsm4(uint32_t& r0, uint32_t& r1,
                                      uint32_t& r2, uint32_t& r3,
                                      uint32_t addr) {
    asm volatile("ldmatrix.sync.aligned.m8n8.x4.shared.b16 {%0,%1,%2,%3}, [%4];\n"
                 : "=r"(r0), "=r"(r1), "=r"(r2), "=r"(r3)
                 : "r"(addr));
}

__device__ __forceinline__ void mma16816(float* d, const uint32_t* a, const uint32_t* b) {
    asm volatile("mma.sync.aligned.m16n8k16.row.col.f32.f16.f16.f32 "
                 "{%0,%1,%2,%3}, {%4,%5,%6,%7}, {%8,%9}, {%0,%1,%2,%3};\n"
                 : "+f"(d[0]), "+f"(d[1]), "+f"(d[2]), "+f"(d[3])
                 : "r"(a[0]), "r"(a[1]), "r"(a[2]), "r"(a[3]),
                   "r"(b[0]), "r"(b[1]));
}

// issue cp.async loads for (A,B) tile kt into pipeline stage s (R8 loader).
__device__ __forceinline__ void load_tiles(int kt, int s, int NK,
                                           int bm, int bn, int K,
                                           uint32_t sA, uint32_t sB,
                                           int ld_row, int ld_chunk) {
    if (kt < NK) {
        const __half* Ag = g_xh;
        const __half* Bg = g_wh;
#pragma unroll
        for (int p = 0; p < 4; p++) {
            int row = ld_row + p * 32;
            uint32_t da = sA + s * SA_BYTES + row * 128 + ((ld_chunk ^ (row & 7)) << 4);
            const void* ga = Ag + (size_t)(bm + row) * K + (size_t)kt * BK + ld_chunk * 8;
            cp_async16(da, ga);
        }
#pragma unroll
        for (int p = 0; p < 4; p++) {
            int row = ld_row + p * 32;
            uint32_t db = sB + s * SB_BYTES + row * 128 + ((ld_chunk ^ (row & 7)) << 4);
            const void* gb = Bg + (size_t)(bn + row) * K + (size_t)kt * BK + ld_chunk * 8;
            cp_async16(db, gb);
        }
    }
    cp_commit();
}

// load A+B fragments for one 16-wide k-step from stage s (R8 code)
__device__ __forceinline__ void load_frags(uint32_t a[4][4], uint32_t b[4][2],
                                           int ks, int s, int wm, int wn,
                                           int lane, uint32_t sA, uint32_t sB) {
#pragma unroll
    for (int mi = 0; mi < 4; mi++) {
        int row = wm * 64 + mi * 16 + (lane & 15);
        int chunk = 2 * ks + (lane >> 4);
        uint32_t addr = sA + s * SA_BYTES + row * 128 + ((chunk ^ (row & 7)) << 4);
        ldsm4(a[mi][0], a[mi][1], a[mi][2], a[mi][3], addr);
    }
#pragma unroll
    for (int nj = 0; nj < 2; nj++) {
        int row = wn * 32 + nj * 16 + (lane & 7) + ((lane >> 4) << 3);
        int chunk = 2 * ks + ((lane >> 3) & 1);
        uint32_t addr = sB + s * SB_BYTES + row * 128 + ((chunk ^ (row & 7)) << 4);
        ldsm4(b[2 * nj][0], b[2 * nj][1], b[2 * nj + 1][0], b[2 * nj + 1][1], addr);
    }
}

// ---------------------- GEMM kernel -----------------------------------------
// 256 threads = 8 warps laid out 2(M) x 4(N). Warp tile 64x32.
// kt-loop unrolled x2 over a 7-stage ring (one barrier per 2 slabs);
// frag dbuf chains across the stage boundary; second cp.async burst is
// interleaved into the mma stream.

__global__ __launch_bounds__(NTHREADS, 1)
void bgemm_kernel(const float* __restrict__ bias, float* __restrict__ C,
                  int M, int N, int K) {
    extern __shared__ __align__(128) unsigned char smem_raw[];
    uint32_t sbase = (uint32_t)__cvta_generic_to_shared(smem_raw);
    uint32_t sA = sbase;
    uint32_t sB = sbase + STAGES * SA_BYTES;

    int tid = threadIdx.x;
    int lane = tid & 31;
    int wid = tid >> 5;
    int wm = wid >> 2;          // 0..1
    int wn = wid & 3;           // 0..3
    int bm = blockIdx.y * BM;
    int bn = blockIdx.x * BN;

    int ld_row = tid >> 3;      // 0..31
    int ld_chunk = tid & 7;     // 0..7

    int NK = K / BK;            // 64 -> 32 outer iters

    // prologue: fill stages 0..4 (5 commit groups; prefetch distance 5)
#pragma unroll
    for (int s = 0; s < 5; s++)
        load_tiles(s, s, NK, bm, bn, K, sA, sB, ld_row, ld_chunk);

    float acc[4][4][4];
#pragma unroll
    for (int mi = 0; mi < 4; mi++)
#pragma unroll
        for (int ni = 0; ni < 4; ni++)
#pragma unroll
            for (int r = 0; r < 4; r++) acc[mi][ni][r] = 0.0f;

    uint32_t a[2][4][4], b[2][4][2];

    for (int j = 0; j < NK / 2; j++) {
        int kt0 = 2 * j;
        int s0 = kt0 % STAGES;
        int s1 = (kt0 + 1) % STAGES;

        // stages s0,s1 resident when <=3 newer groups still outstanding
        cp_wait<3>();
        __syncthreads();

        // critical path first: frags for (s0, ks=0)
        load_frags(a[0], b[0], 0, s0, wm, wn, lane, sA, sB);

        // first prefetch burst (slab kt0+5 -> stage (kt0+5)%7)
        load_tiles(kt0 + 5, (kt0 + 5) % STAGES, NK, bm, bn, K, sA, sB, ld_row, ld_chunk);

        // 8 ks steps spanning stages s0 (0-3) and s1 (4-7); second prefetch
        // burst (slab kt0+6) interleaved after step 1's mma block.
#pragma unroll
        for (int step = 0; step < 8; step++) {
            int cur = step & 1;
            if (step < 7) {
                int nstep = step + 1;
                int ns = (nstep < 4) ? s0 : s1;
                load_frags(a[cur ^ 1], b[cur ^ 1], nstep & 3, ns, wm, wn, lane, sA, sB);
            }
#pragma unroll
            for (int mi = 0; mi < 4; mi++)
#pragma unroll
                for (int ni = 0; ni < 4; ni++)
                    mma16816(acc[mi][ni], a[cur][mi], b[cur][ni]);
            if (step == 1)
                load_tiles(kt0 + 6, (kt0 + 6) % STAGES, NK, bm, bn, K, sA, sB,
                           ld_row, ld_chunk);
        }
    }

    cp_wait<0>();

    // epilogue: add bias (hoisted), store fp32
    int crow = bm + wm * 64;
    int ccol = bn + wn * 32;
    float bh[4][2];
#pragma unroll
    for (int ni = 0; ni < 4; ni++) {
        int c = ccol + ni * 8 + (lane & 3) * 2;
        bh[ni][0] = bias[c];
        bh[ni][1] = bias[c + 1];
    }
#pragma unroll
    for (int mi = 0; mi < 4; mi++) {
        int r = crow + mi * 16 + (lane >> 2);
#pragma unroll
        for (int ni = 0; ni < 4; ni++) {
            int c = ccol + ni * 8 + (lane & 3) * 2;
            float2 v0 = make_float2(acc[mi][ni][0] + bh[ni][0], acc[mi][ni][1] + bh[ni][1]);
            float2 v1 = make_float2(acc[mi][ni][2] + bh[ni][0], acc[mi][ni][3] + bh[ni][1]);
            *reinterpret_cast<float2*>(C + (size_t)r * N + c) = v0;
            *reinterpret_cast<float2*>(C + (size_t)(r + 8) * N + c) = v1;
        }
    }
}

// ---------------------- launch ----------------------------------------------

extern "C" void kernel_launch(void* const* d_in, const int* in_sizes, int n_in,
                              void* d_out, int out_size) {
    const float* x = (const float*)d_in[0];     // [M,K] fp32
    const float* w = (const float*)d_in[1];     // [N,K] fp32
    const float* bias = (const float*)d_in[2];  // [N]   fp32
    float* out = (float*)d_out;                 // [M,N] fp32

    int N = in_sizes[2];
    int K = in_sizes[1] / N;
    int M = in_sizes[0] / K;

    cvt_x_kernel<<<4096, 256>>>((const float4*)x, (M * K) / 4);
    cvt_w_kernel<<<4096, 256>>>((const float4*)w, (N * K) / 4);

    // Persistent attribute; harmless outside capture, inherited by capture.
    cudaFuncSetAttribute(bgemm_kernel,
                         cudaFuncAttributeMaxDynamicSharedMemorySize, SMEM_TOTAL);

    dim3 grid(N / BN, M / BM);
    bgemm_kernel<<<grid, NTHREADS, SMEM_TOTAL>>>(bias, out, M, N, K);
}

// round 16
// speedup vs baseline: 2.1979x; 1.0480x over previous
#include <cuda_runtime.h>
#include <cuda_fp16.h>
#include <cstdint>
#include <cstddef>

// ---------------------------------------------------------------------------
// BinaryLinear: out[M,N] = x[M,K] @ sign(W)[N,K]^T + bias[N]
// M=8192, N=4096, K=4096 (fp32 in/out).
// Round 16: decoupled mbarrier pipeline (no __syncthreads in mainloop).
//   - geometry unchanged (128x128 CTA, 8 warps 2Mx4N, 64x32 warp tile, BK=64)
//   - 7-slab ring, per-slab full/empty mbarriers (arrive count 256)
//   - producers: wait empty -> cp.async x8 -> cp.async.mbarrier.arrive.noinc
//   - consumers: wait full -> frag-dbuf mma -> arrive empty
//   - warps wait on DATA only; convoy from block-wide sync eliminated
// ---------------------------------------------------------------------------

#define BM 128
#define BN 128
#define BK 64
#define STAGES 7
#define NTHREADS 256

#define SA_BYTES (BM * BK * 2)   // 16 KB
#define SB_BYTES (BN * BK * 2)   // 16 KB
#define SMEM_TILES (STAGES * (SA_BYTES + SB_BYTES))   // 224 KB
#define SMEM_TOTAL (SMEM_TILES + 128)                 // + barriers

// Scratch (device globals: no allocation allowed in kernel_launch)
__device__ __half g_xh[8192u * 4096u];   // x as fp16       [M,K]
__device__ __half g_wh[4096u * 4096u];   // sign(W) as fp16 [N,K]

// ---------------------- conversion kernels ---------------------------------

__global__ void cvt_x_kernel(const float4* __restrict__ x, int n4) {
    __half2* dst = reinterpret_cast<__half2*>(g_xh);
    int stride = gridDim.x * blockDim.x;
    for (int i = blockIdx.x * blockDim.x + threadIdx.x; i < n4; i += stride) {
        float4 v = x[i];
        dst[2 * i + 0] = __floats2half2_rn(v.x, v.y);
        dst[2 * i + 1] = __floats2half2_rn(v.z, v.w);
    }
}

__device__ __forceinline__ float fsign(float v) {
    return (v > 0.0f) ? 1.0f : ((v < 0.0f) ? -1.0f : 0.0f);
}

__global__ void cvt_w_kernel(const float4* __restrict__ w, int n4) {
    __half2* dst = reinterpret_cast<__half2*>(g_wh);
    int stride = gridDim.x * blockDim.x;
    for (int i = blockIdx.x * blockDim.x + threadIdx.x; i < n4; i += stride) {
        float4 v = w[i];
        dst[2 * i + 0] = __floats2half2_rn(fsign(v.x), fsign(v.y));
        dst[2 * i + 1] = __floats2half2_rn(fsign(v.z), fsign(v.w));
    }
}

// ---------------------- PTX helpers ----------------------------------------

__device__ __forceinline__ void cp_async16(uint32_t saddr, const void* gaddr) {
    asm volatile("cp.async.cg.shared.global [%0], [%1], 16;\n"
                 :: "r"(saddr), "l"(gaddr));
}

__device__ __forceinline__ void cp_async_mbar_arrive(uint32_t mbar) {
    asm volatile("cp.async.mbarrier.arrive.noinc.shared.b64 [%0];"
                 :: "r"(mbar) : "memory");
}

__device__ __forceinline__ void mbar_init(uint32_t addr, uint32_t count) {
    asm volatile("mbarrier.init.shared.b64 [%0], %1;"
                 :: "r"(addr), "r"(count) : "memory");
}

__device__ __forceinline__ void mbar_arrive(uint32_t addr) {
    asm volatile("mbarrier.arrive.shared.b64 _, [%0];"
                 :: "r"(addr) : "memory");
}

__device__ __forceinline__ void mbar_wait(uint32_t addr, uint32_t parity) {
    asm volatile(
        "{\n\t.reg .pred P;\n\t"
        "WAIT_%=:\n\t"
        "mbarrier.try_wait.parity.acquire.cta.shared::cta.b64 P, [%0], %1, 0x989680;\n\t"
        "@P bra DONE_%=;\n\t"
        "bra WAIT_%=;\n\t"
        "DONE_%=:\n\t}"
        :: "r"(addr), "r"(parity) : "memory");
}

__device__ __forceinline__ void ldsm4(uint32_t& r0, uint32_t& r1,
                                      uint32_t& r2, uint32_t& r3,
                                      uint32_t addr) {
    asm volatile("ldmatrix.sync.aligned.m8n8.x4.shared.b16 {%0,%1,%2,%3}, [%4];\n"
                 : "=r"(r0), "=r"(r1), "=r"(r2), "=r"(r3)
                 : "r"(addr));
}

__device__ __forceinline__ void mma16816(float* d, const uint32_t* a, const uint32_t* b) {
    asm volatile("mma.sync.aligned.m16n8k16.row.col.f32.f16.f16.f32 "
                 "{%0,%1,%2,%3}, {%4,%5,%6,%7}, {%8,%9}, {%0,%1,%2,%3};\n"
                 : "+f"(d[0]), "+f"(d[1]), "+f"(d[2]), "+f"(d[3])
                 : "r"(a[0]), "r"(a[1]), "r"(a[2]), "r"(a[3]),
                   "r"(b[0]), "r"(b[1]));
}

// ---------------------- producer: one slab ----------------------------------
// All 256 threads: wait empty (rev>0), issue 8 cp.async, arrive full.
__device__ __forceinline__ void produce_slab(int q, int NK,
                                             int bm, int bn, int K,
                                             uint32_t sA, uint32_t sB,
                                             uint32_t barBase,
                                             int ld_row, int ld_chunk) {
    if (q >= NK) return;
    unsigned uq = (unsigned)q;
    int s = uq % STAGES;
    unsigned rev = uq / STAGES;
    if (rev > 0)
        mbar_wait(barBase + 64 + s * 8, (rev - 1) & 1);   // empty[s]
#pragma unroll
    for (int p = 0; p < 4; p++) {
        int row = ld_row + p * 32;
        uint32_t da = sA + s * SA_BYTES + row * 128 + ((ld_chunk ^ (row & 7)) << 4);
        const void* ga = g_xh + (size_t)(bm + row) * K + (size_t)q * BK + ld_chunk * 8;
        cp_async16(da, ga);
    }
#pragma unroll
    for (int p = 0; p < 4; p++) {
        int row = ld_row + p * 32;
        uint32_t db = sB + s * SB_BYTES + row * 128 + ((ld_chunk ^ (row & 7)) << 4);
        const void* gb = g_wh + (size_t)(bn + row) * K + (size_t)q * BK + ld_chunk * 8;
        cp_async16(db, gb);
    }
    cp_async_mbar_arrive(barBase + s * 8);                // full[s]
}

// load A+B fragments for one 16-wide k-step from stage s
__device__ __forceinline__ void load_frags(uint32_t a[4][4], uint32_t b[4][2],
                                           int ks, int s, int wm, int wn,
                                           int lane, uint32_t sA, uint32_t sB) {
#pragma unroll
    for (int mi = 0; mi < 4; mi++) {
        int row = wm * 64 + mi * 16 + (lane & 15);
        int chunk = 2 * ks + (lane >> 4);
        uint32_t addr = sA + s * SA_BYTES + row * 128 + ((chunk ^ (row & 7)) << 4);
        ldsm4(a[mi][0], a[mi][1], a[mi][2], a[mi][3], addr);
    }
#pragma unroll
    for (int nj = 0; nj < 2; nj++) {
        int row = wn * 32 + nj * 16 + (lane & 7) + ((lane >> 4) << 3);
        int chunk = 2 * ks + ((lane >> 3) & 1);
        uint32_t addr = sB + s * SB_BYTES + row * 128 + ((chunk ^ (row & 7)) << 4);
        ldsm4(b[2 * nj][0], b[2 * nj][1], b[2 * nj + 1][0], b[2 * nj + 1][1], addr);
    }
}

// ---------------------- GEMM kernel -----------------------------------------
// 256 threads = 8 warps laid out 2(M) x 4(N). Warp tile 64x32.
// Decoupled pipeline: consumers gate on full[s], producers on empty[s];
// no __syncthreads in the mainloop.

__global__ __launch_bounds__(NTHREADS, 1)
void bgemm_kernel(const float* __restrict__ bias, float* __restrict__ C,
                  int M, int N, int K) {
    extern __shared__ __align__(128) unsigned char smem_raw[];
    uint32_t sbase = (uint32_t)__cvta_generic_to_shared(smem_raw);
    uint32_t sA = sbase;
    uint32_t sB = sbase + STAGES * SA_BYTES;
    uint32_t barBase = sbase + SMEM_TILES;   // full[7] @ +0, empty[7] @ +64

    int tid = threadIdx.x;
    int lane = tid & 31;
    int wid = tid >> 5;
    int wm = wid >> 2;          // 0..1
    int wn = wid & 3;           // 0..3
    int bm = blockIdx.y * BM;
    int bn = blockIdx.x * BN;

    int ld_row = tid >> 3;      // 0..31
    int ld_chunk = tid & 7;     // 0..7

    int NK = K / BK;            // 64 -> 32 outer iters

    if (tid == 0) {
#pragma unroll
        for (int s = 0; s < STAGES; s++) {
            mbar_init(barBase + s * 8, NTHREADS);        // full[s]
            mbar_init(barBase + 64 + s * 8, NTHREADS);   // empty[s]
        }
    }
    __syncthreads();   // one-time: barriers visible to all threads

    // prologue: fill slabs 0..4 (prefetch distance 5; rev 0, no empty wait)
#pragma unroll
    for (int q = 0; q < 5; q++)
        produce_slab(q, NK, bm, bn, K, sA, sB, barBase, ld_row, ld_chunk);

    float acc[4][4][4];
#pragma unroll
    for (int mi = 0; mi < 4; mi++)
#pragma unroll
        for (int ni = 0; ni < 4; ni++)
#pragma unroll
            for (int r = 0; r < 4; r++) acc[mi][ni][r] = 0.0f;

    uint32_t a[2][4][4], b[2][4][2];

    for (int j = 0; j < NK / 2; j++) {
        int kt0 = 2 * j;
        unsigned s0 = (unsigned)kt0 % STAGES;
        unsigned rev0 = (unsigned)kt0 / STAGES;
        unsigned s1 = (unsigned)(kt0 + 1) % STAGES;
        unsigned rev1 = (unsigned)(kt0 + 1) / STAGES;

        // consume stage s0
        mbar_wait(barBase + s0 * 8, rev0 & 1);           // full[s0]
        load_frags(a[0], b[0], 0, s0, wm, wn, lane, sA, sB);

        // producer burst 1 (slab kt0+5)
        produce_slab(kt0 + 5, NK, bm, bn, K, sA, sB, barBase, ld_row, ld_chunk);

        // steps 0..2: stage s0, prefetch next frags
#pragma unroll
        for (int step = 0; step < 3; step++) {
            int cur = step & 1;
            load_frags(a[cur ^ 1], b[cur ^ 1], step + 1, s0, wm, wn, lane, sA, sB);
#pragma unroll
            for (int mi = 0; mi < 4; mi++)
#pragma unroll
                for (int ni = 0; ni < 4; ni++)
                    mma16816(acc[mi][ni], a[cur][mi], b[cur][ni]);
            if (step == 1)   // producer burst 2 interleaved
                produce_slab(kt0 + 6, NK, bm, bn, K, sA, sB, barBase, ld_row, ld_chunk);
        }

        // stage s1 must be resident before prefetching its frags
        mbar_wait(barBase + s1 * 8, rev1 & 1);           // full[s1]

        // step 3: last mma on s0 data; prefetch (s1, ks0)
        {
            int cur = 1;   // step 3
            load_frags(a[0], b[0], 0, s1, wm, wn, lane, sA, sB);
#pragma unroll
            for (int mi = 0; mi < 4; mi++)
#pragma unroll
                for (int ni = 0; ni < 4; ni++)
                    mma16816(acc[mi][ni], a[cur][mi], b[cur][ni]);
        }
        mbar_arrive(barBase + 64 + s0 * 8);              // empty[s0]

        // steps 4..7: stage s1
#pragma unroll
        for (int step = 4; step < 8; step++) {
            int cur = step & 1;
            if (step < 7)
                load_frags(a[cur ^ 1], b[cur ^ 1], (step + 1) & 3, s1,
                           wm, wn, lane, sA, sB);
#pragma unroll
            for (int mi = 0; mi < 4; mi++)
#pragma unroll
                for (int ni = 0; ni < 4; ni++)
                    mma16816(acc[mi][ni], a[cur][mi], b[cur][ni]);
        }
        mbar_arrive(barBase + 64 + s1 * 8);              // empty[s1]
    }

    // epilogue: add bias (hoisted), store fp32
    int crow = bm + wm * 64;
    int ccol = bn + wn * 32;
    float bh[4][2];
#pragma unroll
    for (int ni = 0; ni < 4; ni++) {
        int c = ccol + ni * 8 + (lane & 3) * 2;
        bh[ni][0] = bias[c];
        bh[ni][1] = bias[c + 1];
    }
#pragma unroll
    for (int mi = 0; mi < 4; mi++) {
        int r = crow + mi * 16 + (lane >> 2);
#pragma unroll
        for (int ni = 0; ni < 4; ni++) {
            int c = ccol + ni * 8 + (lane & 3) * 2;
            float2 v0 = make_float2(acc[mi][ni][0] + bh[ni][0], acc[mi][ni][1] + bh[ni][1]);
            float2 v1 = make_float2(acc[mi][ni][2] + bh[ni][0], acc[mi][ni][3] + bh[ni][1]);
            *reinterpret_cast<float2*>(C + (size_t)r * N + c) = v0;
            *reinterpret_cast<float2*>(C + (size_t)(r + 8) * N + c) = v1;
        }
    }
}

// ---------------------- launch ----------------------------------------------

extern "C" void kernel_launch(void* const* d_in, const int* in_sizes, int n_in,
                              void* d_out, int out_size) {
    const float* x = (const float*)d_in[0];     // [M,K] fp32
    const float* w = (const float*)d_in[1];     // [N,K] fp32
    const float* bias = (const float*)d_in[2];  // [N]   fp32
    float* out = (float*)d_out;                 // [M,N] fp32

    int N = in_sizes[2];
    int K = in_sizes[1] / N;
    int M = in_sizes[0] / K;

    cvt_x_kernel<<<4096, 256>>>((const float4*)x, (M * K) / 4);
    cvt_w_kernel<<<4096, 256>>>((const float4*)w, (N * K) / 4);

    // Persistent attribute; harmless outside capture, inherited by capture.
    cudaFuncSetAttribute(bgemm_kernel,
                         cudaFuncAttributeMaxDynamicSharedMemorySize, SMEM_TOTAL);

    dim3 grid(N / BN, M / BM);
    bgemm_kernel<<<grid, NTHREADS, SMEM_TOTAL>>>(bias, out, M, N, K);
}